// round 8
// baseline (speedup 1.0000x reference)
#include <cuda_runtime.h>
#include <cstdint>

#define B_     16
#define P_     784
#define D_     10000
#define NW_    316         // valid packed words: 79 groups x 4 (permuted ballot layout)
#define WPITCH 320
#define NROW_  1040        // 784 pw rows + 256 vw rows
#define NXB_   25          // extra k_pack blocks for x quantize
#define NSPL   16          // p splits (49 each)
#define NG     10          // wordgroups of 32 words

// ---- device scratch ----
__device__ unsigned g_pack[NROW_ * WPITCH];          // [row][word] row-major (1.33 MB)
__device__ unsigned g_idxr[NSPL * 16 * 16];          // level bytes [ch][b][64B] (16 KB)
__device__ unsigned g_part2[NSPL * 6 * 16 * WPITCH]; // 6-plane partials (1.97 MB)
__device__ unsigned g_cnt[NG];                       // arrival counters (self-resetting)

__device__ __forceinline__ unsigned maj3(unsigned a, unsigned b, unsigned c) {
    return (a & b) | (a & c) | (b & c);   // single LOP3
}

// ============ K1: pack sign bits (row-major), quantize x ============
// Word W: bit l <-> column 128*(W>>2) + 4*l + (W&3)
__global__ __launch_bounds__(512)
void k_pack(const float* __restrict__ x,
            const float* __restrict__ pw,
            const float* __restrict__ vw)
{
    int bid = blockIdx.x;
    if (bid < NROW_) {
        const float* src = (bid < P_) ? (pw + (size_t)bid * D_)
                                      : (vw + (size_t)(bid - P_) * D_);
        int wid = threadIdx.x >> 5, lane = threadIdx.x & 31;

        float4 f[5];                        // MLP=5 per thread
        #pragma unroll
        for (int k = 0; k < 5; k++) {
            int g   = wid + k * 16;
            int col = g * 128 + lane * 4;
            bool ok = (g < 79) && (col + 3 < D_);
            f[k] = ok ? *reinterpret_cast<const float4*>(src + col)
                      : make_float4(1.f, 1.f, 1.f, 1.f);
        }
        #pragma unroll
        for (int k = 0; k < 5; k++) {
            int g = wid + k * 16;
            if (g < 79) {                   // warp-uniform
                unsigned m0 = __ballot_sync(0xffffffffu, f[k].x < 0.f);
                unsigned m1 = __ballot_sync(0xffffffffu, f[k].y < 0.f);
                unsigned m2 = __ballot_sync(0xffffffffu, f[k].z < 0.f);
                unsigned m3 = __ballot_sync(0xffffffffu, f[k].w < 0.f);
                if (lane < 4) {
                    unsigned mm = (lane == 0) ? m0 : (lane == 1) ? m1
                                 : (lane == 2) ? m2 : m3;
                    g_pack[bid * WPITCH + g * 4 + lane] = mm;   // 16B per group
                }
            }
        }
    } else {
        int i = (bid - NROW_) * 512 + threadIdx.x;
        if (i < B_ * P_) {
            int b = i / P_, p = i - b * P_;
            int ch = p / 49, j = p - ch * 49;
            int q = __float2int_rn(x[i] * 255.0f);   // matches jnp.round (RN-even)
            q = max(0, min(255, q));
            reinterpret_cast<unsigned char*>(g_idxr)[((ch * 16 + b) << 6) + j] =
                (unsigned char)q;
        }
    }
}

// ============ K2 (fused): conflict-free accumulate + last-block combine ============
// Block = (wordgroup g of 32 words, split sp of 49 p). Warp = b, lane = word.
__global__ __launch_bounds__(512)
void k_acc(float* __restrict__ out)
{
    __shared__ unsigned vw_s[256 * 32];   // [lev][word]  32 KB, bank = lane
    __shared__ unsigned pw_s[49 * 32];    // [p][word]    6.1 KB
    __shared__ unsigned br_s[16 * 32];    // sign masks [b][word] (last block)
    __shared__ unsigned last_f;

    const int g  = blockIdx.x >> 4;
    const int sp = blockIdx.x & 15;
    const int t  = threadIdx.x;
    const int b  = t >> 5;                // warp id = batch
    const int lane = t & 31;              // lane = word within group

    // ---- coalesced tile fills (128B rows) ----
    const unsigned* vwbase = g_pack + (size_t)P_ * WPITCH + g * 32;
    #pragma unroll
    for (int r = b; r < 256; r += 16)
        vw_s[r * 32 + lane] = vwbase[r * WPITCH + lane];
    const unsigned* pwbase = g_pack + (size_t)(sp * 49) * WPITCH + g * 32;
    #pragma unroll
    for (int r = b; r < 49; r += 16)
        pw_s[r * 32 + lane] = pwbase[r * WPITCH + lane];

    // ---- level bytes for (sp, b): 49 bytes -> registers (uniform, L1-hot) ----
    unsigned u[13];
    {
        const uint4* ib = reinterpret_cast<const uint4*>(g_idxr + (sp * 16 + b) * 16);
        uint4 a0 = ib[0], a1 = ib[1], a2 = ib[2];
        u[0]=a0.x; u[1]=a0.y; u[2]=a0.z;  u[3]=a0.w;
        u[4]=a1.x; u[5]=a1.y; u[6]=a1.z;  u[7]=a1.w;
        u[8]=a2.x; u[9]=a2.y; u[10]=a2.z; u[11]=a2.w;
        u[12] = g_idxr[(sp * 16 + b) * 16 + 12];
    }
    __syncthreads();

    // ---- 49 positions = 7 CSA groups of 7, zero bank conflicts ----
    unsigned cc0 = 0, cc1 = 0, cc2 = 0, cc3 = 0, cc4 = 0, cc5 = 0;
    #pragma unroll
    for (int gg = 0; gg < 7; gg++) {
        unsigned s[7];
        #pragma unroll
        for (int jj = 0; jj < 7; jj++) {
            int j = gg * 7 + jj;                       // compile-time constant
            unsigned lev = (u[j >> 2] >> ((j & 3) * 8)) & 255u;
            s[jj] = vw_s[lev * 32 + lane] ^ pw_s[j * 32 + lane];
        }
        unsigned t1s = s[0] ^ s[1] ^ s[2], t1c = maj3(s[0], s[1], s[2]);
        unsigned t2s = s[3] ^ s[4] ^ s[5], t2c = maj3(s[3], s[4], s[5]);
        unsigned q0  = t1s ^ t2s ^ s[6],   t3c = maj3(t1s, t2s, s[6]);
        unsigned q1  = t1c ^ t2c ^ t3c;
        unsigned q2  = maj3(t1c, t2c, t3c);
        unsigned c = cc0 & q0;            cc0 ^= q0;
        unsigned n1 = maj3(cc1, q1, c);   cc1 = cc1 ^ q1 ^ c;  c = n1;
        unsigned n2 = maj3(cc2, q2, c);   cc2 = cc2 ^ q2 ^ c;  c = n2;
        unsigned n3 = cc3 & c;            cc3 ^= c;            c = n3;
        unsigned n4 = cc4 & c;            cc4 ^= c;            c = n4;
        cc5 ^= c;                                              // max 49 < 64
    }

    // ---- write 6-plane partials (fully coalesced) ----
    {
        size_t base = (size_t)((sp * 6) * 16 + b) * WPITCH + g * 32 + lane;
        g_part2[base]              = cc0;
        g_part2[base + 16*WPITCH]  = cc1;
        g_part2[base + 32*WPITCH]  = cc2;
        g_part2[base + 48*WPITCH]  = cc3;
        g_part2[base + 64*WPITCH]  = cc4;
        g_part2[base + 80*WPITCH]  = cc5;
    }
    __threadfence();
    __syncthreads();
    if (t == 0) {
        unsigned old = atomicAdd(&g_cnt[g], 1u);
        last_f = (old == NSPL - 1) ? 1u : 0u;
    }
    __syncthreads();
    if (!last_f) return;
    if (t == 0) g_cnt[g] = 0;             // reset for next launch (deterministic)
    __threadfence();
    __syncthreads();

    // ---- last block: 16-way bit-sliced combine -> 10 planes ----
    {
        unsigned P0=0,P1=0,P2=0,P3=0,P4=0,P5=0,P6=0,P7=0,P8=0,P9=0;
        #pragma unroll
        for (int s2 = 0; s2 < NSPL; s2++) {
            size_t base = (size_t)((s2 * 6) * 16 + b) * WPITCH + g * 32 + lane;
            unsigned a0 = __ldcg(&g_part2[base]);
            unsigned a1 = __ldcg(&g_part2[base + 16*WPITCH]);
            unsigned a2 = __ldcg(&g_part2[base + 32*WPITCH]);
            unsigned a3 = __ldcg(&g_part2[base + 48*WPITCH]);
            unsigned a4 = __ldcg(&g_part2[base + 64*WPITCH]);
            unsigned a5 = __ldcg(&g_part2[base + 80*WPITCH]);
            unsigned c, n;
            c = P0 & a0;           P0 ^= a0;
            n = maj3(P1, a1, c);   P1 = P1 ^ a1 ^ c;  c = n;
            n = maj3(P2, a2, c);   P2 = P2 ^ a2 ^ c;  c = n;
            n = maj3(P3, a3, c);   P3 = P3 ^ a3 ^ c;  c = n;
            n = maj3(P4, a4, c);   P4 = P4 ^ a4 ^ c;  c = n;
            n = maj3(P5, a5, c);   P5 = P5 ^ a5 ^ c;  c = n;
            n = P6 & c;  P6 ^= c;  c = n;
            n = P7 & c;  P7 ^= c;  c = n;
            n = P8 & c;  P8 ^= c;  c = n;
            P9 ^= c;                                   // max 784 < 1024
        }
        // borrow of (cnt - 392); 392 = bits 3,7,8.  br=1 <=> cnt<392 <=> +1
        unsigned br = 0;
        br = ~P0 & br;  br = ~P1 & br;  br = ~P2 & br;
        br = ~P3 | br;
        br = ~P4 & br;  br = ~P5 & br;  br = ~P6 & br;
        br = ~P7 | br;  br = ~P8 | br;
        br = ~P9 & br;
        br_s[b * 32 + lane] = br;
    }
    __syncthreads();

    // ---- coalesced sign store: this group covers cols [g*1024, g*1024+1024) ----
    {
        const int C0 = g * 1024;
        const int w0 = (lane >> 2) * 4;
        float* orow = out + (size_t)b * D_;
        #pragma unroll
        for (int k = 0; k < 8; k++) {
            int c = C0 + lane * 32 + k * 4;
            if (c < D_) {                              // c,D_ mult of 4 -> whole f4 ok
                unsigned l = (unsigned)((lane * 8 + k) & 31);
                float4 v;
                v.x = __uint_as_float(0x3F800000u | ((((br_s[b*32+w0+0] >> l) & 1u) ^ 1u) << 31));
                v.y = __uint_as_float(0x3F800000u | ((((br_s[b*32+w0+1] >> l) & 1u) ^ 1u) << 31));
                v.z = __uint_as_float(0x3F800000u | ((((br_s[b*32+w0+2] >> l) & 1u) ^ 1u) << 31));
                v.w = __uint_as_float(0x3F800000u | ((((br_s[b*32+w0+3] >> l) & 1u) ^ 1u) << 31));
                *reinterpret_cast<float4*>(orow + c) = v;
            }
        }
    }
}

extern "C" void kernel_launch(void* const* d_in, const int* in_sizes, int n_in,
                              void* d_out, int out_size)
{
    (void)in_sizes; (void)n_in; (void)out_size;
    const float* x  = (const float*)d_in[0];   // (16, 28, 28)
    const float* pw = (const float*)d_in[1];   // (784, 10000)
    const float* vw = (const float*)d_in[2];   // (256, 10000)
    float* out = (float*)d_out;                // (16, 10000)

    k_pack<<<NROW_ + NXB_, 512>>>(x, pw, vw);
    k_acc<<<NG * NSPL, 512>>>(out);
}

// round 10
// speedup vs baseline: 1.2748x; 1.2748x over previous
#include <cuda_runtime.h>
#include <cstdint>

#define B_     16
#define P_     784
#define D_     10000
#define WPITCH 320
#define NROW_  1040        // 784 pw rows + 256 vw rows
#define NRB_   520         // k_pack blocks: 2 rows each
#define NXB_   25          // extra k_pack blocks for x quantize
#define NG2    20          // wordgroups of 16 words
#define SPB    8           // sp splits per group (98 p each, 2 chunks of 49)

// ---- device scratch ----
__device__ unsigned g_pack[NROW_ * WPITCH];       // [row][word] row-major (1.33 MB)
__device__ unsigned g_idxr[16 * 16 * 16];         // level bytes [ch][b][64B] (16 KB)
__device__ unsigned g_part3[NG2 * SPB * 7 * 256]; // 7-plane partials (1.15 MB)
__device__ unsigned g_cnt[NG2];                   // arrival counters (self-resetting)

__device__ __forceinline__ unsigned maj3(unsigned a, unsigned b, unsigned c) {
    return (a & b) | (a & c) | (b & c);   // single LOP3
}

// ============ K1: pack sign bits (row-major), quantize x ============
// Word W: bit l <-> column 128*(W>>2) + 4*l + (W&3)
__global__ __launch_bounds__(512, 2)
void k_pack(const float* __restrict__ x,
            const float* __restrict__ pw,
            const float* __restrict__ vw)
{
    int bid = blockIdx.x;
    if (bid < NRB_) {
        int wid = threadIdx.x >> 5, lane = threadIdx.x & 31;
        int row = bid * 2 + (wid >> 3);           // warps 0-7 row A, 8-15 row B
        int wq  = wid & 7;
        const float* src = (row < P_) ? (pw + (size_t)row * D_)
                                      : (vw + (size_t)(row - P_) * D_);
        float4 f[10];                              // MLP=10 per thread
        #pragma unroll
        for (int k = 0; k < 10; k++) {
            int g   = wq + k * 8;
            int col = g * 128 + lane * 4;
            bool ok = (g < 79) && (col + 3 < D_);
            f[k] = ok ? *reinterpret_cast<const float4*>(src + col)
                      : make_float4(1.f, 1.f, 1.f, 1.f);
        }
        #pragma unroll
        for (int k = 0; k < 10; k++) {
            int g = wq + k * 8;
            if (g < 79) {                          // warp-uniform
                unsigned m0 = __ballot_sync(0xffffffffu, f[k].x < 0.f);
                unsigned m1 = __ballot_sync(0xffffffffu, f[k].y < 0.f);
                unsigned m2 = __ballot_sync(0xffffffffu, f[k].z < 0.f);
                unsigned m3 = __ballot_sync(0xffffffffu, f[k].w < 0.f);
                if (lane < 4) {
                    unsigned mm = (lane == 0) ? m0 : (lane == 1) ? m1
                                 : (lane == 2) ? m2 : m3;
                    g_pack[row * WPITCH + g * 4 + lane] = mm;
                }
            }
        }
    } else {
        int i = (bid - NRB_) * 512 + threadIdx.x;
        if (i < B_ * P_) {
            int b = i / P_, p = i - b * P_;
            int ch = p / 49, j = p - ch * 49;
            int q = __float2int_rn(x[i] * 255.0f);   // matches jnp.round (RN-even)
            q = max(0, min(255, q));
            reinterpret_cast<unsigned char*>(g_idxr)[((ch * 16 + b) << 6) + j] =
                (unsigned char)q;
        }
    }
}

// ============ K2 (fused): accumulate + last-block combine + sign store ============
// Block = (wordgroup g of 16 words, sp of 98 p). Warp = b; lane = (w, ph).
__global__ __launch_bounds__(512, 2)
void k_acc(float* __restrict__ out)
{
    __shared__ unsigned vw_s[256 * 17];   // [lev][16 words, pad 17]  17 KB
    __shared__ unsigned pw_s[98 * 16];    // [p][16 words]            6.3 KB
    __shared__ unsigned br_s[256];        // sign masks [b][w] (last block)
    __shared__ unsigned last_f;

    const int g    = blockIdx.x >> 3;
    const int sp   = blockIdx.x & 7;
    const int t    = threadIdx.x;
    const int b    = t >> 5;              // warp = batch
    const int lane = t & 31;
    const int w    = lane & 15;           // word within group
    const int ph   = lane >> 4;           // p-half (chunk select)

    // ---- tile fills ----
    for (int i = t; i < 256 * 16; i += 512) {
        int lev = i >> 4, ww = i & 15;
        vw_s[lev * 17 + ww] = g_pack[(size_t)(P_ + lev) * WPITCH + g * 16 + ww];
    }
    for (int i = t; i < 98 * 16; i += 512)
        pw_s[i] = g_pack[(size_t)(sp * 98 + (i >> 4)) * WPITCH + g * 16 + (i & 15)];

    // ---- level bytes for chunk c = 2sp+ph, batch b -> registers ----
    const int c = sp * 2 + ph;
    unsigned u[13];
    {
        const uint4* ib = reinterpret_cast<const uint4*>(g_idxr + (c * 16 + b) * 16);
        uint4 a0 = ib[0], a1 = ib[1], a2 = ib[2];
        u[0]=a0.x; u[1]=a0.y; u[2]=a0.z;  u[3]=a0.w;
        u[4]=a1.x; u[5]=a1.y; u[6]=a1.z;  u[7]=a1.w;
        u[8]=a2.x; u[9]=a2.y; u[10]=a2.z; u[11]=a2.w;
        u[12] = g_idxr[(c * 16 + b) * 16 + 12];
    }
    __syncthreads();

    // ---- 49 positions = 7 CSA groups of 7 ----
    const unsigned* pwr = pw_s + ph * 49 * 16 + w;   // halves bank-disjoint
    unsigned cc0 = 0, cc1 = 0, cc2 = 0, cc3 = 0, cc4 = 0, cc5 = 0;
    #pragma unroll
    for (int gg = 0; gg < 7; gg++) {
        unsigned s[7];
        #pragma unroll
        for (int jj = 0; jj < 7; jj++) {
            int j = gg * 7 + jj;                      // compile-time constant
            unsigned lev = (u[j >> 2] >> ((j & 3) * 8)) & 255u;
            s[jj] = vw_s[lev * 17 + w] ^ pwr[j * 16];
        }
        unsigned t1s = s[0] ^ s[1] ^ s[2], t1c = maj3(s[0], s[1], s[2]);
        unsigned t2s = s[3] ^ s[4] ^ s[5], t2c = maj3(s[3], s[4], s[5]);
        unsigned q0  = t1s ^ t2s ^ s[6],   t3c = maj3(t1s, t2s, s[6]);
        unsigned q1  = t1c ^ t2c ^ t3c;
        unsigned q2  = maj3(t1c, t2c, t3c);
        unsigned cr = cc0 & q0;            cc0 ^= q0;
        unsigned n1 = maj3(cc1, q1, cr);   cc1 = cc1 ^ q1 ^ cr;  cr = n1;
        unsigned n2 = maj3(cc2, q2, cr);   cc2 = cc2 ^ q2 ^ cr;  cr = n2;
        unsigned n3 = cc3 & cr;            cc3 ^= cr;            cr = n3;
        unsigned n4 = cc4 & cr;            cc4 ^= cr;            cr = n4;
        cc5 ^= cr;                                               // max 49 < 64
    }

    // ---- merge p-halves via shfl (lane ^ 16): 6+6 planes -> 7 (max 98) ----
    unsigned cc6;
    {
        unsigned d0 = __shfl_xor_sync(0xffffffffu, cc0, 16);
        unsigned d1 = __shfl_xor_sync(0xffffffffu, cc1, 16);
        unsigned d2 = __shfl_xor_sync(0xffffffffu, cc2, 16);
        unsigned d3 = __shfl_xor_sync(0xffffffffu, cc3, 16);
        unsigned d4 = __shfl_xor_sync(0xffffffffu, cc4, 16);
        unsigned d5 = __shfl_xor_sync(0xffffffffu, cc5, 16);
        unsigned cr, n;
        cr = cc0 & d0;            cc0 ^= d0;
        n = maj3(cc1, d1, cr);    cc1 = cc1 ^ d1 ^ cr;  cr = n;
        n = maj3(cc2, d2, cr);    cc2 = cc2 ^ d2 ^ cr;  cr = n;
        n = maj3(cc3, d3, cr);    cc3 = cc3 ^ d3 ^ cr;  cr = n;
        n = maj3(cc4, d4, cr);    cc4 = cc4 ^ d4 ^ cr;  cr = n;
        n = maj3(cc5, d5, cr);    cc5 = cc5 ^ d5 ^ cr;  cr = n;
        cc6 = cr;
    }
    if (lane < 16) {
        unsigned base = ((g * SPB + sp) * 7) * 256 + b * 16 + lane;
        g_part3[base]           = cc0;
        g_part3[base + 1 * 256] = cc1;
        g_part3[base + 2 * 256] = cc2;
        g_part3[base + 3 * 256] = cc3;
        g_part3[base + 4 * 256] = cc4;
        g_part3[base + 5 * 256] = cc5;
        g_part3[base + 6 * 256] = cc6;
    }
    __threadfence();
    __syncthreads();
    if (t == 0) {
        unsigned old = atomicAdd(&g_cnt[g], 1u);
        last_f = (old == SPB - 1) ? 1u : 0u;
    }
    __syncthreads();
    if (!last_f) return;
    if (t == 0) g_cnt[g] = 0;             // reset for next launch (deterministic)

    // ---- last block per g: 8-way combine -> 10 planes, compare vs 392 ----
    if (t < 256) {                         // t = b2*16 + w2
        unsigned P0=0,P1=0,P2=0,P3=0,P4=0,P5=0,P6=0,P7=0,P8=0,P9=0;
        #pragma unroll
        for (int s2 = 0; s2 < SPB; s2++) {
            unsigned base = ((g * SPB + s2) * 7) * 256 + t;
            unsigned a0 = __ldcg(&g_part3[base]);
            unsigned a1 = __ldcg(&g_part3[base + 1 * 256]);
            unsigned a2 = __ldcg(&g_part3[base + 2 * 256]);
            unsigned a3 = __ldcg(&g_part3[base + 3 * 256]);
            unsigned a4 = __ldcg(&g_part3[base + 4 * 256]);
            unsigned a5 = __ldcg(&g_part3[base + 5 * 256]);
            unsigned a6 = __ldcg(&g_part3[base + 6 * 256]);
            unsigned cr, n;
            cr = P0 & a0;           P0 ^= a0;
            n = maj3(P1, a1, cr);   P1 = P1 ^ a1 ^ cr;  cr = n;
            n = maj3(P2, a2, cr);   P2 = P2 ^ a2 ^ cr;  cr = n;
            n = maj3(P3, a3, cr);   P3 = P3 ^ a3 ^ cr;  cr = n;
            n = maj3(P4, a4, cr);   P4 = P4 ^ a4 ^ cr;  cr = n;
            n = maj3(P5, a5, cr);   P5 = P5 ^ a5 ^ cr;  cr = n;
            n = maj3(P6, a6, cr);   P6 = P6 ^ a6 ^ cr;  cr = n;
            n = P7 & cr;  P7 ^= cr;  cr = n;
            n = P8 & cr;  P8 ^= cr;  cr = n;
            P9 ^= cr;                                    // max 784 < 1024
        }
        // borrow of (cnt - 392); 392 = bits 3,7,8.  br=1 <=> cnt<392 <=> +1
        unsigned br = 0;
        br = ~P0 & br;  br = ~P1 & br;  br = ~P2 & br;
        br = ~P3 | br;
        br = ~P4 & br;  br = ~P5 & br;  br = ~P6 & br;
        br = ~P7 | br;  br = ~P8 | br;
        br = ~P9 & br;
        br_s[t] = br;
    }
    __syncthreads();

    // ---- coalesced sign store: group g covers cols [512g, 512g+512) ----
    {
        float* orow = out + (size_t)b * D_;
        #pragma unroll
        for (int k = 0; k < 4; k++) {
            int col = g * 512 + k * 128 + lane * 4;
            if (col < D_) {                            // col,D_ mult of 4
                const unsigned* brq = &br_s[b * 16 + k * 4];
                float4 v;
                v.x = __uint_as_float(0x3F800000u | ((((brq[0] >> lane) & 1u) ^ 1u) << 31));
                v.y = __uint_as_float(0x3F800000u | ((((brq[1] >> lane) & 1u) ^ 1u) << 31));
                v.z = __uint_as_float(0x3F800000u | ((((brq[2] >> lane) & 1u) ^ 1u) << 31));
                v.w = __uint_as_float(0x3F800000u | ((((brq[3] >> lane) & 1u) ^ 1u) << 31));
                *reinterpret_cast<float4*>(orow + col) = v;
            }
        }
    }
}

extern "C" void kernel_launch(void* const* d_in, const int* in_sizes, int n_in,
                              void* d_out, int out_size)
{
    (void)in_sizes; (void)n_in; (void)out_size;
    const float* x  = (const float*)d_in[0];   // (16, 28, 28)
    const float* pw = (const float*)d_in[1];   // (784, 10000)
    const float* vw = (const float*)d_in[2];   // (256, 10000)
    float* out = (float*)d_out;                // (16, 10000)

    k_pack<<<NRB_ + NXB_, 512>>>(x, pw, vw);
    k_acc<<<NG2 * SPB, 512>>>(out);
}

// round 11
// speedup vs baseline: 1.3917x; 1.0917x over previous
#include <cuda_runtime.h>
#include <cstdint>

#define B_     16
#define P_     784
#define D_     10000
#define WPITCH 320
#define NROW_  1040        // 784 pw rows + 256 vw rows
#define NRB_   520         // k_pack blocks: 2 rows each
#define NXB_   25          // extra k_pack blocks for x quantize
#define NG3    40          // wordgroups of 8 words
#define SPB3   7           // sp splits per group (112 p each, 4 sub-chunks of 28)

// ---- device scratch ----
__device__ unsigned g_pack[NROW_ * WPITCH];        // [row][word] row-major (1.33 MB)
__device__ unsigned g_idxr[28 * 16 * 8];           // level bytes [ch][b][32B] (14.3 KB)
__device__ unsigned g_part3[NG3 * SPB3 * 7 * 128]; // 7-plane partials (1.0 MB)
__device__ unsigned g_cnt[NG3];                    // arrival counters (self-resetting)

__device__ __forceinline__ unsigned maj3(unsigned a, unsigned b, unsigned c) {
    return (a & b) | (a & c) | (b & c);   // single LOP3
}

// ============ K1: pack sign bits (row-major), quantize x ============
// Word W: bit l <-> column 128*(W>>2) + 4*l + (W&3)
__global__ __launch_bounds__(512, 2)
void k_pack(const float* __restrict__ x,
            const float* __restrict__ pw,
            const float* __restrict__ vw)
{
    int bid = blockIdx.x;
    if (bid < NRB_) {
        int wid = threadIdx.x >> 5, lane = threadIdx.x & 31;
        int row = bid * 2 + (wid >> 3);           // warps 0-7 row A, 8-15 row B
        int wq  = wid & 7;
        const float* src = (row < P_) ? (pw + (size_t)row * D_)
                                      : (vw + (size_t)(row - P_) * D_);
        float4 f[10];                              // MLP=10 per thread
        #pragma unroll
        for (int k = 0; k < 10; k++) {
            int g   = wq + k * 8;
            int col = g * 128 + lane * 4;
            bool ok = (g < 79) && (col + 3 < D_);
            f[k] = ok ? *reinterpret_cast<const float4*>(src + col)
                      : make_float4(1.f, 1.f, 1.f, 1.f);
        }
        #pragma unroll
        for (int k = 0; k < 10; k++) {
            int g = wq + k * 8;
            if (g < 79) {                          // warp-uniform
                unsigned m0 = __ballot_sync(0xffffffffu, f[k].x < 0.f);
                unsigned m1 = __ballot_sync(0xffffffffu, f[k].y < 0.f);
                unsigned m2 = __ballot_sync(0xffffffffu, f[k].z < 0.f);
                unsigned m3 = __ballot_sync(0xffffffffu, f[k].w < 0.f);
                if (lane < 4) {
                    unsigned mm = (lane == 0) ? m0 : (lane == 1) ? m1
                                 : (lane == 2) ? m2 : m3;
                    g_pack[row * WPITCH + g * 4 + lane] = mm;
                }
            }
        }
    } else {
        int i = (bid - NRB_) * 512 + threadIdx.x;
        if (i < B_ * P_) {
            int b = i / P_, p = i - b * P_;
            int ch = p / 28, j = p - ch * 28;      // 28 chunks of 28
            int q = __float2int_rn(x[i] * 255.0f); // matches jnp.round (RN-even)
            q = max(0, min(255, q));
            reinterpret_cast<unsigned char*>(g_idxr)[ch * 512 + b * 32 + j] =
                (unsigned char)q;
        }
    }
}

// ============ K2 (fused): accumulate + last-block combine + sign store ============
// Block = (wordgroup g of 8 words, sp of 112 p). Warp = b; lane = (q, w).
__global__ __launch_bounds__(512, 2)
void k_acc(float* __restrict__ out)
{
    __shared__ unsigned vw_s[256 * 9];    // [lev][8 words pad 9]   9.2 KB
    __shared__ unsigned pw_s[28 * 32];    // [j][q][w] bank = lane  3.6 KB
    __shared__ unsigned br_s[128];        // sign masks [b][w] (last block)
    __shared__ unsigned last_f;

    const int g    = blockIdx.x / 7;
    const int sp   = blockIdx.x - g * 7;
    const int t    = threadIdx.x;
    const int b    = t >> 5;              // warp = batch
    const int lane = t & 31;
    const int q    = lane >> 3;           // sub-chunk (28 p each)
    const int w    = lane & 7;            // word within group

    // ---- tile fills ----
    for (int i = t; i < 2048; i += 512)
        vw_s[(i >> 3) * 9 + (i & 7)] =
            g_pack[(size_t)(P_ + (i >> 3)) * WPITCH + g * 8 + (i & 7)];
    for (int i = t; i < 28 * 32; i += 512) {
        int j = i >> 5, qw = i & 31;
        pw_s[i] = g_pack[(size_t)(sp * 112 + (qw >> 3) * 28 + j) * WPITCH
                         + g * 8 + (qw & 7)];
    }

    // ---- level bytes for chunk ch = 4sp+q, batch b -> registers ----
    unsigned u[7];
    {
        const uint4* ib = reinterpret_cast<const uint4*>(
            g_idxr + ((sp * 4 + q) * 16 + b) * 8);
        uint4 a0 = ib[0], a1 = ib[1];
        u[0]=a0.x; u[1]=a0.y; u[2]=a0.z; u[3]=a0.w;
        u[4]=a1.x; u[5]=a1.y; u[6]=a1.z;
    }
    __syncthreads();

    // ---- 28 positions = 4 CSA groups of 7 (pw LDS conflict-free: bank=lane) ----
    unsigned cc0 = 0, cc1 = 0, cc2 = 0, cc3 = 0, cc4 = 0;
    #pragma unroll
    for (int gg = 0; gg < 4; gg++) {
        unsigned s[7];
        #pragma unroll
        for (int jj = 0; jj < 7; jj++) {
            int j = gg * 7 + jj;                      // compile-time constant
            unsigned lev = (u[j >> 2] >> ((j & 3) * 8)) & 255u;
            s[jj] = vw_s[lev * 9 + w] ^ pw_s[j * 32 + lane];
        }
        unsigned t1s = s[0] ^ s[1] ^ s[2], t1c = maj3(s[0], s[1], s[2]);
        unsigned t2s = s[3] ^ s[4] ^ s[5], t2c = maj3(s[3], s[4], s[5]);
        unsigned q0  = t1s ^ t2s ^ s[6],   t3c = maj3(t1s, t2s, s[6]);
        unsigned q1  = t1c ^ t2c ^ t3c;
        unsigned q2  = maj3(t1c, t2c, t3c);
        unsigned cr = cc0 & q0;            cc0 ^= q0;
        unsigned n1 = maj3(cc1, q1, cr);   cc1 = cc1 ^ q1 ^ cr;  cr = n1;
        unsigned n2 = maj3(cc2, q2, cr);   cc2 = cc2 ^ q2 ^ cr;  cr = n2;
        unsigned n3 = cc3 & cr;            cc3 ^= cr;            cr = n3;
        cc4 ^= cr;                                               // max 28 < 32
    }

    // ---- combine q sub-chunks: xor8 (5+5 -> 6), xor16 (6+6 -> 7 planes) ----
    unsigned cc5, cc6;
    {
        unsigned d0 = __shfl_xor_sync(0xffffffffu, cc0, 8);
        unsigned d1 = __shfl_xor_sync(0xffffffffu, cc1, 8);
        unsigned d2 = __shfl_xor_sync(0xffffffffu, cc2, 8);
        unsigned d3 = __shfl_xor_sync(0xffffffffu, cc3, 8);
        unsigned d4 = __shfl_xor_sync(0xffffffffu, cc4, 8);
        unsigned cr, n;
        cr = cc0 & d0;            cc0 ^= d0;
        n = maj3(cc1, d1, cr);    cc1 = cc1 ^ d1 ^ cr;  cr = n;
        n = maj3(cc2, d2, cr);    cc2 = cc2 ^ d2 ^ cr;  cr = n;
        n = maj3(cc3, d3, cr);    cc3 = cc3 ^ d3 ^ cr;  cr = n;
        n = maj3(cc4, d4, cr);    cc4 = cc4 ^ d4 ^ cr;  cr = n;
        cc5 = cr;                                        // max 56 < 64
    }
    {
        unsigned d0 = __shfl_xor_sync(0xffffffffu, cc0, 16);
        unsigned d1 = __shfl_xor_sync(0xffffffffu, cc1, 16);
        unsigned d2 = __shfl_xor_sync(0xffffffffu, cc2, 16);
        unsigned d3 = __shfl_xor_sync(0xffffffffu, cc3, 16);
        unsigned d4 = __shfl_xor_sync(0xffffffffu, cc4, 16);
        unsigned d5 = __shfl_xor_sync(0xffffffffu, cc5, 16);
        unsigned cr, n;
        cr = cc0 & d0;            cc0 ^= d0;
        n = maj3(cc1, d1, cr);    cc1 = cc1 ^ d1 ^ cr;  cr = n;
        n = maj3(cc2, d2, cr);    cc2 = cc2 ^ d2 ^ cr;  cr = n;
        n = maj3(cc3, d3, cr);    cc3 = cc3 ^ d3 ^ cr;  cr = n;
        n = maj3(cc4, d4, cr);    cc4 = cc4 ^ d4 ^ cr;  cr = n;
        n = maj3(cc5, d5, cr);    cc5 = cc5 ^ d5 ^ cr;  cr = n;
        cc6 = cr;                                        // max 112 < 128
    }
    if (lane < 8) {                        // lanes 0-7: canonical (b, w) partials
        unsigned base = ((g * SPB3 + sp) * 7) * 128 + b * 8 + w;
        g_part3[base]           = cc0;
        g_part3[base + 1 * 128] = cc1;
        g_part3[base + 2 * 128] = cc2;
        g_part3[base + 3 * 128] = cc3;
        g_part3[base + 4 * 128] = cc4;
        g_part3[base + 5 * 128] = cc5;
        g_part3[base + 6 * 128] = cc6;
    }
    __threadfence();
    __syncthreads();
    if (t == 0) {
        unsigned old = atomicAdd(&g_cnt[g], 1u);
        last_f = (old == SPB3 - 1) ? 1u : 0u;
    }
    __syncthreads();
    if (!last_f) return;
    if (t == 0) g_cnt[g] = 0;             // reset for next launch (deterministic)

    // ---- last block per g: 7-way combine -> 10 planes, compare vs 392 ----
    if (t < 128) {                         // t = b2*8 + w2
        unsigned P0=0,P1=0,P2=0,P3=0,P4=0,P5=0,P6=0,P7=0,P8=0,P9=0;
        #pragma unroll
        for (int s2 = 0; s2 < SPB3; s2++) {
            unsigned base = ((g * SPB3 + s2) * 7) * 128 + t;
            unsigned a0 = __ldcg(&g_part3[base]);
            unsigned a1 = __ldcg(&g_part3[base + 1 * 128]);
            unsigned a2 = __ldcg(&g_part3[base + 2 * 128]);
            unsigned a3 = __ldcg(&g_part3[base + 3 * 128]);
            unsigned a4 = __ldcg(&g_part3[base + 4 * 128]);
            unsigned a5 = __ldcg(&g_part3[base + 5 * 128]);
            unsigned a6 = __ldcg(&g_part3[base + 6 * 128]);
            unsigned cr, n;
            cr = P0 & a0;           P0 ^= a0;
            n = maj3(P1, a1, cr);   P1 = P1 ^ a1 ^ cr;  cr = n;
            n = maj3(P2, a2, cr);   P2 = P2 ^ a2 ^ cr;  cr = n;
            n = maj3(P3, a3, cr);   P3 = P3 ^ a3 ^ cr;  cr = n;
            n = maj3(P4, a4, cr);   P4 = P4 ^ a4 ^ cr;  cr = n;
            n = maj3(P5, a5, cr);   P5 = P5 ^ a5 ^ cr;  cr = n;
            n = maj3(P6, a6, cr);   P6 = P6 ^ a6 ^ cr;  cr = n;
            n = P7 & cr;  P7 ^= cr;  cr = n;
            n = P8 & cr;  P8 ^= cr;  cr = n;
            P9 ^= cr;                                    // max 784 < 1024
        }
        // borrow of (cnt - 392); 392 = bits 3,7,8.  br=1 <=> cnt<392 <=> +1
        unsigned br = 0;
        br = ~P0 & br;  br = ~P1 & br;  br = ~P2 & br;
        br = ~P3 | br;
        br = ~P4 & br;  br = ~P5 & br;  br = ~P6 & br;
        br = ~P7 | br;  br = ~P8 | br;
        br = ~P9 & br;
        br_s[t] = br;
    }
    __syncthreads();

    // ---- coalesced sign store: group g covers cols [256g, 256g+256) ----
    {
        float* orow = out + (size_t)b * D_;
        #pragma unroll
        for (int sub = 0; sub < 2; sub++) {
            int col0 = g * 256 + sub * 128 + lane * 4;
            if (col0 + 3 < D_) {
                const unsigned* brq = &br_s[b * 8 + sub * 4];
                float4 v;
                v.x = __uint_as_float(0x3F800000u | ((((brq[0] >> lane) & 1u) ^ 1u) << 31));
                v.y = __uint_as_float(0x3F800000u | ((((brq[1] >> lane) & 1u) ^ 1u) << 31));
                v.z = __uint_as_float(0x3F800000u | ((((brq[2] >> lane) & 1u) ^ 1u) << 31));
                v.w = __uint_as_float(0x3F800000u | ((((brq[3] >> lane) & 1u) ^ 1u) << 31));
                *reinterpret_cast<float4*>(orow + col0) = v;
            }
        }
    }
}

extern "C" void kernel_launch(void* const* d_in, const int* in_sizes, int n_in,
                              void* d_out, int out_size)
{
    (void)in_sizes; (void)n_in; (void)out_size;
    const float* x  = (const float*)d_in[0];   // (16, 28, 28)
    const float* pw = (const float*)d_in[1];   // (784, 10000)
    const float* vw = (const float*)d_in[2];   // (256, 10000)
    float* out = (float*)d_out;                // (16, 10000)

    k_pack<<<NRB_ + NXB_, 512>>>(x, pw, vw);
    k_acc<<<NG3 * SPB3, 512>>>(out);
}